// round 15
// baseline (speedup 1.0000x reference)
#include <cuda_runtime.h>
#include <cuda_fp16.h>
#include <cstdint>

// FeaturesLoss hybrid: per SM one 256-thread CTA. Warps 0-3 = legacy tensor
// (mma.sync m16n8k16 f16 acc) on tiles [0,NSPLIT); warps 4-7 = HFMA2 fma-pipe
// GEMM on tiles [NSPLIT,NBLK). Both pipes run concurrently. Deterministic:
// static tile->path split, per-tile partials, fixed-order finalize.

#define BN    8192
#define DIM   128
#define TM    128
#define NT    (BN / TM)             // 64
#define NBLK  (NT * (NT + 1) / 2)   // 2080
#define NSPLIT 1264                 // tensor tiles [0,NSPLIT)
#define MARGIN 2.0f
#define NPERS 152

// ---- tensor group smem (same as R14) ----
#define NCHUNK 4
#define PITCH  80
#define PITCHW 20
#define ACH    (TM * PITCH)         // 10240
#define BCH    (TM * PITCH)
#define T_A    0
#define T_B    (NCHUNK * ACH)       // 40960
#define T_STG  (T_B + NCHUNK * BCH) // 81920
#define STGSZ  2048
// ---- fma group smem ----
#define F_BASE (T_STG + 2 * STGSZ)  // 86016
#define F_SLOT 32768                // A chunk 16K + B chunk 16K
#define F_BOFF 16384
#define F_STG  (F_BASE + 2 * F_SLOT)// 151552
#define SM_TOT (F_STG + 2 * STGSZ)  // 155648

__device__ float      g_sq[BN];
__device__ int        g_lab[BN];
__device__ uint32_t   g_f16[BN * DIM / 2];   // row-major packed half2
__device__ __half     g_f16t[DIM * BN];      // k-major transpose (2 MB)
__device__ float      g_partials[NBLK];
__device__ long long  g_poscnt[NBLK];
__device__ unsigned   g_tick_t, g_tick_f;

__device__ __forceinline__ uint32_t smem_u32(const void* p) {
    uint32_t a;
    asm("{ .reg .u64 t; cvta.to.shared.u64 t, %1; cvt.u32.u64 %0, t; }" : "=r"(a) : "l"(p));
    return a;
}
__device__ __forceinline__ void cp16(uint32_t dst, const void* src) {
    asm volatile("cp.async.cg.shared.global [%0], [%1], 16;" :: "r"(dst), "l"(src));
}
__device__ __forceinline__ void cp_commit() {
    asm volatile("cp.async.commit_group;" ::: "memory");
}
template<int N> __device__ __forceinline__ void cp_wait() {
    asm volatile("cp.async.wait_group %0;" :: "n"(N) : "memory");
}
#define BAR_T() asm volatile("bar.sync 1, 128;" ::: "memory")
#define BAR_F() asm volatile("bar.sync 2, 128;" ::: "memory")

__device__ __forceinline__ void mma_f16acc(uint32_t c[2], uint32_t a0, uint32_t a1,
                                           uint32_t a2, uint32_t a3,
                                           uint32_t b0, uint32_t b1) {
    asm volatile(
        "mma.sync.aligned.m16n8k16.row.col.f16.f16.f16.f16 "
        "{%0,%1}, {%2,%3,%4,%5}, {%6,%7}, {%0,%1};"
        : "+r"(c[0]), "+r"(c[1])
        : "r"(a0), "r"(a1), "r"(a2), "r"(a3), "r"(b0), "r"(b1));
}
__device__ __forceinline__ void decode_tile(int idx, int& i0, int& j0) {
    int bi = 0;
    while (idx >= NT - bi) { idx -= NT - bi; bi++; }
    i0 = bi * TM;
    j0 = (bi + idx) * TM;
}
// loss for one pair (shared by both paths)
__device__ __forceinline__ void pair_loss(float dot, float sqi, float sqj,
                                          int li, int lj, float& lsum, int& lcnt) {
    float d2 = fmaxf(sqi + sqj - 2.0f * dot, 0.0f);
    if (li == lj) { lsum += d2; lcnt++; }
    else if (d2 < MARGIN * MARGIN) {   // ~never taken (8 sigma)
        float h = MARGIN - sqrtf(d2);
        lsum += h * h;
    }
}

// ---------------------------------------------------------------------------
// Kernel 0: norms, labels, fp16 row-major copy + k-major transpose.
// ---------------------------------------------------------------------------
__global__ void prep_kernel(const float* __restrict__ F,
                            const void* __restrict__ labels_raw) {
    if (blockIdx.x == 0 && threadIdx.x == 0) { g_tick_t = 0; g_tick_f = 0; }

    int warp = (blockIdx.x * blockDim.x + threadIdx.x) >> 5;
    int lane = threadIdx.x & 31;
    if (warp >= BN) return;

    const int* w = (const int*)labels_raw;
    int probe = w[2 * lane + 1];
    unsigned is64 = __all_sync(0xffffffffu, probe == 0);

    const float4* row = (const float4*)(F + (size_t)warp * DIM);
    float4 f = row[lane];

    __half h0 = __float2half(f.x), h1 = __float2half(f.y);
    __half h2 = __float2half(f.z), h3 = __float2half(f.w);
    __half2 p0 = __halves2half2(h0, h1), p1 = __halves2half2(h2, h3);
    uint2 hp = { *(uint32_t*)&p0, *(uint32_t*)&p1 };
    *(uint2*)&g_f16[(size_t)warp * 64 + lane * 2] = hp;

    // k-major transpose (scattered 2B stores)
    int kb = lane * 4;
    g_f16t[(size_t)(kb + 0) * BN + warp] = h0;
    g_f16t[(size_t)(kb + 1) * BN + warp] = h1;
    g_f16t[(size_t)(kb + 2) * BN + warp] = h2;
    g_f16t[(size_t)(kb + 3) * BN + warp] = h3;

    float s = f.x * f.x + f.y * f.y + f.z * f.z + f.w * f.w;
    #pragma unroll
    for (int off = 16; off; off >>= 1)
        s += __shfl_xor_sync(0xffffffffu, s, off);

    if (lane == 0) {
        g_sq[warp] = s;
        int lab;
        if (is64) lab = (int)((const long long*)labels_raw)[warp];
        else      lab = w[warp];
        g_lab[warp] = lab;
    }
}

// ---------------------------------------------------------------------------
// tensor group chunk issue (K=32 fp16, threads 0..127)
__device__ __forceinline__ void t_issue(uint32_t sbase, int i0, int j0, int c, int t) {
    const char* P = (const char*)g_f16;
    #pragma unroll
    for (int s = t; s < TM * 4; s += 128) {
        int r = s >> 2, q = s & 3;
        cp16(sbase + T_A + c * ACH + r * PITCH + q * 16,
             P + (size_t)(i0 + r) * 256 + c * 64 + q * 16);
    }
    #pragma unroll
    for (int s = t; s < TM * 4; s += 128) {
        int r = s >> 2, q = s & 3;
        cp16(sbase + T_B + c * BCH + r * PITCH + q * 16,
             P + (size_t)(j0 + r) * 256 + c * 64 + q * 16);
    }
}
// fma group chunk issue (K=64: A row-major 128x128B, B k-major 64x256B)
__device__ __forceinline__ void f_issue(uint32_t sbase, int i0, int j0,
                                        int c, int slot, int ft) {
    const char* P  = (const char*)g_f16;
    const char* Pt = (const char*)g_f16t;
    uint32_t ab = sbase + F_BASE + slot * F_SLOT;
    uint32_t bb = ab + F_BOFF;
    #pragma unroll
    for (int s = ft; s < TM * 8; s += 128) {        // A: 1024 segs
        int r = s >> 3, q = s & 7;
        cp16(ab + r * 128 + q * 16,
             P + (size_t)(i0 + r) * 256 + c * 128 + q * 16);
    }
    #pragma unroll
    for (int s = ft; s < 64 * 16; s += 128) {       // B: 1024 segs
        int r = s >> 4, q = s & 15;
        cp16(bb + r * 256 + q * 16,
             Pt + ((size_t)(c * 64 + r) * BN + j0) * 2 + q * 16);
    }
}

// ---------------------------------------------------------------------------
__global__ void __launch_bounds__(256, 1)
tile_kernel() {
    extern __shared__ char smem[];
    uint32_t sbase = smem_u32(smem);
    int t = threadIdx.x;

    __shared__ int   s_tick_t, s_tick_f;
    __shared__ float rbuf_t[4], rbuf_f[4];
    __shared__ int   rcnt_t[4], rcnt_f[4];

    if (t < 128) {
        // ================= TENSOR GROUP (warps 0-3) =================
        int wid = t >> 5, lane = t & 31;
        int gid = lane >> 2, tig = lane & 3;
        int wm = wid & 1, wn = wid >> 1;
        int mbase = wm * 64, nbase = wn * 64;

        if (t == 0) s_tick_t = (int)atomicAdd(&g_tick_t, 1u);
        BAR_T();
        int cur = s_tick_t;
        if (cur >= NSPLIT) return;
        int i0, j0;
        decode_tile(cur, i0, j0);

        #pragma unroll
        for (int c = 0; c < NCHUNK; c++) { t_issue(sbase, i0, j0, c, t); cp_commit(); }

        int parity = 0;
        for (;;) {
            if (t == 0) s_tick_t = (int)atomicAdd(&g_tick_t, 1u);
            {
                char* stg = smem + T_STG + parity * STGSZ;
                ((float*)stg)[t]          = g_sq[i0 + t];
                ((float*)(stg + 512))[t]  = g_sq[j0 + t];
                ((int*)(stg + 1024))[t]   = g_lab[i0 + t];
                ((int*)(stg + 1536))[t]   = g_lab[j0 + t];
            }
            BAR_T();
            int nxt = s_tick_t;
            int ni0 = 0, nj0 = 0;
            bool more = (nxt < NSPLIT);
            if (more) decode_tile(nxt, ni0, nj0);

            uint32_t acc[4][8][2];
            #pragma unroll
            for (int mf = 0; mf < 4; mf++)
                #pragma unroll
                for (int nf = 0; nf < 8; nf++) { acc[mf][nf][0] = 0u; acc[mf][nf][1] = 0u; }

            #pragma unroll
            for (int c = 0; c < NCHUNK; c++) {
                cp_wait<3>();
                BAR_T();
                const uint32_t* Ac = (const uint32_t*)(smem + T_A + c * ACH);
                const uint32_t* Bc = (const uint32_t*)(smem + T_B + c * BCH);
                #pragma unroll
                for (int g = 0; g < 2; g++) {
                    int kb = g * 8;
                    uint32_t a[4][4];
                    #pragma unroll
                    for (int mf = 0; mf < 4; mf++) {
                        const uint32_t* r0 = Ac + (size_t)(mbase + 16 * mf + gid) * PITCHW + kb;
                        const uint32_t* r1 = Ac + (size_t)(mbase + 16 * mf + gid + 8) * PITCHW + kb;
                        a[mf][0] = r0[tig]; a[mf][1] = r1[tig];
                        a[mf][2] = r0[tig + 4]; a[mf][3] = r1[tig + 4];
                    }
                    uint32_t b[8][2];
                    #pragma unroll
                    for (int nf = 0; nf < 8; nf++) {
                        const uint32_t* rn = Bc + (size_t)(nbase + 8 * nf + gid) * PITCHW + kb;
                        b[nf][0] = rn[tig]; b[nf][1] = rn[tig + 4];
                    }
                    #pragma unroll
                    for (int mf = 0; mf < 4; mf++)
                        #pragma unroll
                        for (int nf = 0; nf < 8; nf++)
                            mma_f16acc(acc[mf][nf], a[mf][0], a[mf][1], a[mf][2], a[mf][3],
                                       b[nf][0], b[nf][1]);
                }
                BAR_T();
                if (more) t_issue(sbase, ni0, nj0, c, t);
                cp_commit();
            }

            const char* stg = smem + T_STG + parity * STGSZ;
            const float* sqI = (const float*)stg;
            const float* sqJ = (const float*)(stg + 512);
            const int*   lbI = (const int*)(stg + 1024);
            const int*   lbJ = (const int*)(stg + 1536);

            float lsum = 0.0f; int lcnt = 0;
            #pragma unroll
            for (int mf = 0; mf < 4; mf++)
                #pragma unroll
                for (int rr = 0; rr < 2; rr++) {
                    int m = mbase + 16 * mf + gid + 8 * rr;
                    int gi = i0 + m;
                    float sqi = sqI[m]; int li = lbI[m];
                    #pragma unroll
                    for (int nf = 0; nf < 8; nf++) {
                        uint32_t reg = acc[mf][nf][rr];
                        float2 dv = __half22float2(*(__half2*)&reg);
                        #pragma unroll
                        for (int cc = 0; cc < 2; cc++) {
                            int n = nbase + 8 * nf + tig * 2 + cc;
                            int gj = j0 + n;
                            if (gj <= gi) continue;
                            pair_loss(cc ? dv.y : dv.x, sqi, sqJ[n], li, lbJ[n], lsum, lcnt);
                        }
                    }
                }

            #pragma unroll
            for (int off = 16; off; off >>= 1) {
                lsum += __shfl_xor_sync(0xffffffffu, lsum, off);
                lcnt += __shfl_xor_sync(0xffffffffu, lcnt, off);
            }
            if (lane == 0) { rbuf_t[wid] = lsum; rcnt_t[wid] = lcnt; }
            BAR_T();
            if (t == 0) {
                float s = 0.0f; long long c = 0;
                #pragma unroll
                for (int wd = 0; wd < 4; wd++) { s += rbuf_t[wd]; c += rcnt_t[wd]; }
                g_partials[cur] = s * 2.0f;
                g_poscnt[cur]   = c * 2LL;
            }
            if (!more) break;
            cur = nxt; i0 = ni0; j0 = nj0; parity ^= 1;
        }
    } else {
        // ================= FMA GROUP (warps 4-7, HFMA2) =================
        int ft = t - 128;
        int wid = ft >> 5, lane = ft & 31;
        int rg = ft >> 3, cg = ft & 7;      // rows rg*8+., cols cg*16+.

        if (ft == 0) s_tick_f = NSPLIT + (int)atomicAdd(&g_tick_f, 1u);
        BAR_F();
        int cur = s_tick_f;
        if (cur >= NBLK) return;
        int i0, j0;
        decode_tile(cur, i0, j0);

        f_issue(sbase, i0, j0, 0, 0, ft); cp_commit();
        f_issue(sbase, i0, j0, 1, 1, ft); cp_commit();

        int parity = 0;
        for (;;) {
            if (ft == 0) s_tick_f = NSPLIT + (int)atomicAdd(&g_tick_f, 1u);
            {
                char* stg = smem + F_STG + parity * STGSZ;
                ((float*)stg)[ft]         = g_sq[i0 + ft];
                ((float*)(stg + 512))[ft] = g_sq[j0 + ft];
                ((int*)(stg + 1024))[ft]  = g_lab[i0 + ft];
                ((int*)(stg + 1536))[ft]  = g_lab[j0 + ft];
            }
            BAR_F();
            int nxt = s_tick_f;
            int ni0 = 0, nj0 = 0;
            bool more = (nxt < NBLK);
            if (more) decode_tile(nxt, ni0, nj0);

            __half2 acc[8][8];
            #pragma unroll
            for (int r = 0; r < 8; r++)
                #pragma unroll
                for (int cp = 0; cp < 8; cp++) acc[r][cp] = __half2(__float2half(0.f), __float2half(0.f));

            #pragma unroll
            for (int c = 0; c < 2; c++) {
                cp_wait<1>();
                BAR_F();
                const char* Ab = smem + F_BASE + c * F_SLOT;
                const char* Bb = Ab + F_BOFF;

                for (int g = 0; g < 8; g++) {       // 8 k per group, loop rolled
                    uint4 aw[8];
                    #pragma unroll
                    for (int r = 0; r < 8; r++)
                        aw[r] = *(const uint4*)(Ab + (rg * 8 + r) * 128 + g * 16);
                    #pragma unroll
                    for (int kk = 0; kk < 8; kk++) {
                        const char* brow = Bb + (g * 8 + kk) * 256 + cg * 32;
                        uint4 bv0 = *(const uint4*)brow;
                        uint4 bv1 = *(const uint4*)(brow + 16);
                        __half2 b[8];
                        b[0] = *(__half2*)&bv0.x; b[1] = *(__half2*)&bv0.y;
                        b[2] = *(__half2*)&bv0.z; b[3] = *(__half2*)&bv0.w;
                        b[4] = *(__half2*)&bv1.x; b[5] = *(__half2*)&bv1.y;
                        b[6] = *(__half2*)&bv1.z; b[7] = *(__half2*)&bv1.w;
                        #pragma unroll
                        for (int r = 0; r < 8; r++) {
                            uint32_t w = ((const uint32_t*)&aw[r])[kk >> 1];
                            uint32_t sp = __byte_perm(w, w, (kk & 1) ? 0x3232 : 0x1010);
                            __half2 sa = *(__half2*)&sp;
                            #pragma unroll
                            for (int cp = 0; cp < 8; cp++)
                                acc[r][cp] = __hfma2(sa, b[cp], acc[r][cp]);
                        }
                    }
                }
                BAR_F();
                if (more) f_issue(sbase, ni0, nj0, c, c, ft);
                cp_commit();
            }

            const char* stg = smem + F_STG + parity * STGSZ;
            const float* sqI = (const float*)stg;
            const float* sqJ = (const float*)(stg + 512);
            const int*   lbI = (const int*)(stg + 1024);
            const int*   lbJ = (const int*)(stg + 1536);

            float lsum = 0.0f; int lcnt = 0;
            #pragma unroll
            for (int r = 0; r < 8; r++) {
                int m = rg * 8 + r;
                int gi = i0 + m;
                float sqi = sqI[m]; int li = lbI[m];
                #pragma unroll
                for (int cp = 0; cp < 8; cp++) {
                    float2 dv = __half22float2(acc[r][cp]);
                    #pragma unroll
                    for (int h = 0; h < 2; h++) {
                        int n = cg * 16 + cp * 2 + h;
                        int gj = j0 + n;
                        if (gj <= gi) continue;
                        pair_loss(h ? dv.y : dv.x, sqi, sqJ[n], li, lbJ[n], lsum, lcnt);
                    }
                }
            }

            #pragma unroll
            for (int off = 16; off; off >>= 1) {
                lsum += __shfl_xor_sync(0xffffffffu, lsum, off);
                lcnt += __shfl_xor_sync(0xffffffffu, lcnt, off);
            }
            if (lane == 0) { rbuf_f[wid] = lsum; rcnt_f[wid] = lcnt; }
            BAR_F();
            if (ft == 0) {
                float s = 0.0f; long long c = 0;
                #pragma unroll
                for (int wd = 0; wd < 4; wd++) { s += rbuf_f[wd]; c += rcnt_f[wd]; }
                g_partials[cur] = s * 2.0f;
                g_poscnt[cur]   = c * 2LL;
            }
            if (!more) break;
            cur = nxt; i0 = ni0; j0 = nj0; parity ^= 1;
        }
    }
}

// ---------------------------------------------------------------------------
__global__ void finalize_kernel(float* __restrict__ out) {
    int t = threadIdx.x;
    double s = 0.0; long long c = 0;
    for (int i = t; i < NBLK; i += 256) {
        s += (double)g_partials[i];
        c += g_poscnt[i];
    }
    __shared__ double    sd[256];
    __shared__ long long sc[256];
    sd[t] = s; sc[t] = c;
    __syncthreads();
    for (int off = 128; off; off >>= 1) {
        if (t < off) { sd[t] += sd[t + off]; sc[t] += sc[t + off]; }
        __syncthreads();
    }
    if (t == 0) {
        double total = sd[0];
        double denom = (double)((long long)BN * (BN - 1));
        out[0] = (float)(sc[0] > 0 ? total / denom : total);
    }
}

// ---------------------------------------------------------------------------
extern "C" void kernel_launch(void* const* d_in, const int* in_sizes, int n_in,
                              void* d_out, int out_size) {
    const float* F      = (const float*)d_in[0];
    const void*  labels = d_in[1];
    float*       out    = (float*)d_out;

    cudaFuncSetAttribute(tile_kernel,
                         cudaFuncAttributeMaxDynamicSharedMemorySize, SM_TOT);

    prep_kernel<<<BN / 8, 256>>>(F, labels);
    tile_kernel<<<NPERS, 256, SM_TOT>>>();
    finalize_kernel<<<1, 256>>>(out);
}

// round 16
// speedup vs baseline: 2.1110x; 2.1110x over previous
#include <cuda_runtime.h>
#include <cuda_fp16.h>
#include <cstdint>

// FeaturesLoss: mma.sync m16n8k16 fp16/f32acc, persistent 128-thread CTAs
// (2/SM), continuous 4-buffer cp.async ring with refill-before-compute
// (1 barrier per chunk), 128x128 tiles (64x64/warp), ordered-pair (j>i, x2),
// deterministic per-tile partials + fixed-order finalize.

#define BN    8192
#define DIM   128
#define TM    128
#define NT    (BN / TM)             // 64
#define NBLK  (NT * (NT + 1) / 2)   // 2080 upper-tri tiles
#define MARGIN 2.0f
#define NPERS (152 * 2)

#define NCHUNK 4                    // K chunks of 32 (fp16: 64 B per row)
#define PITCH  80                   // bytes per row per chunk (20 words)
#define PITCHW 20
#define ACH    (TM * PITCH)         // 10240
#define BCH    (TM * PITCH)         // 10240
#define SM_A   0
#define SM_B   (NCHUNK * ACH)       // 40960
#define SM_STG (SM_B + NCHUNK * BCH)// 81920
#define SM_TOT (SM_STG + 2048)      // 83968 B per CTA (x2 CTAs = 164 KB/SM)

__device__ float      g_sq[BN];
__device__ int        g_lab[BN];
__device__ uint32_t   g_f16[BN * DIM / 2];   // packed half2, natural k order
__device__ float      g_partials[NBLK];
__device__ long long  g_poscnt[NBLK];
__device__ unsigned   g_ticket;

__device__ __forceinline__ uint32_t smem_u32(const void* p) {
    uint32_t a;
    asm("{ .reg .u64 t; cvta.to.shared.u64 t, %1; cvt.u32.u64 %0, t; }" : "=r"(a) : "l"(p));
    return a;
}
__device__ __forceinline__ void cp16(uint32_t dst, const void* src) {
    asm volatile("cp.async.cg.shared.global [%0], [%1], 16;" :: "r"(dst), "l"(src));
}
__device__ __forceinline__ void cp_commit() {
    asm volatile("cp.async.commit_group;" ::: "memory");
}
template<int N> __device__ __forceinline__ void cp_wait() {
    asm volatile("cp.async.wait_group %0;" :: "n"(N) : "memory");
}
__device__ __forceinline__ void mma_f16(float c[4], uint32_t a0, uint32_t a1,
                                        uint32_t a2, uint32_t a3,
                                        uint32_t b0, uint32_t b1) {
    asm volatile(
        "mma.sync.aligned.m16n8k16.row.col.f32.f16.f16.f32 "
        "{%0,%1,%2,%3}, {%4,%5,%6,%7}, {%8,%9}, {%0,%1,%2,%3};"
        : "+f"(c[0]), "+f"(c[1]), "+f"(c[2]), "+f"(c[3])
        : "r"(a0), "r"(a1), "r"(a2), "r"(a3), "r"(b0), "r"(b1));
}
__device__ __forceinline__ void decode_tile(int idx, int& i0, int& j0) {
    int bi = 0;
    while (idx >= NT - bi) { idx -= NT - bi; bi++; }
    i0 = bi * TM;
    j0 = (bi + idx) * TM;
}

// ---------------------------------------------------------------------------
// Kernel 0: norms (exact fp32), labels (int64/int32 probe), fp16 packed copy.
// ---------------------------------------------------------------------------
__global__ void prep_kernel(const float* __restrict__ F,
                            const void* __restrict__ labels_raw) {
    if (blockIdx.x == 0 && threadIdx.x == 0) g_ticket = 0;  // reset per replay

    int warp = (blockIdx.x * blockDim.x + threadIdx.x) >> 5;
    int lane = threadIdx.x & 31;
    if (warp >= BN) return;

    const int* w = (const int*)labels_raw;
    int probe = w[2 * lane + 1];
    unsigned is64 = __all_sync(0xffffffffu, probe == 0);

    const float4* row = (const float4*)(F + (size_t)warp * DIM);
    float4 f = row[lane];

    __half2 h0 = __floats2half2_rn(f.x, f.y);
    __half2 h1 = __floats2half2_rn(f.z, f.w);
    uint2 hp = { *(uint32_t*)&h0, *(uint32_t*)&h1 };
    *(uint2*)&g_f16[(size_t)warp * 64 + lane * 2] = hp;

    float s = f.x * f.x + f.y * f.y + f.z * f.z + f.w * f.w;
    #pragma unroll
    for (int off = 16; off; off >>= 1)
        s += __shfl_xor_sync(0xffffffffu, s, off);

    if (lane == 0) {
        g_sq[warp] = s;
        int lab;
        if (is64) lab = (int)((const long long*)labels_raw)[warp];
        else      lab = w[warp];
        g_lab[warp] = lab;
    }
}

// ---------------------------------------------------------------------------
// Issue cp.async for K=32 chunk c of tile (i0,j0) into ring buffer `buf`.
__device__ __forceinline__ void issue_chunk(uint32_t sbase, int i0, int j0,
                                            int c, int buf, int t) {
    const char* P = (const char*)g_f16;           // 256 B per feature row
    #pragma unroll
    for (int s = t; s < TM * 4; s += 128) {
        int r = s >> 2, q = s & 3;
        cp16(sbase + SM_A + buf * ACH + r * PITCH + q * 16,
             P + (size_t)(i0 + r) * 256 + c * 64 + q * 16);
    }
    #pragma unroll
    for (int s = t; s < TM * 4; s += 128) {
        int r = s >> 2, q = s & 3;
        cp16(sbase + SM_B + buf * BCH + r * PITCH + q * 16,
             P + (size_t)(j0 + r) * 256 + c * 64 + q * 16);
    }
}

// ---------------------------------------------------------------------------
__global__ void __launch_bounds__(128, 2)
tile_kernel() {
    extern __shared__ char smem[];
    uint32_t sbase = smem_u32(smem);

    int t = threadIdx.x;
    int wid = t >> 5, lane = t & 31;
    int gid = lane >> 2, tig = lane & 3;
    int wm = wid & 1, wn = wid >> 1;     // 2x2 grid of 64x64 subtiles
    int mbase = wm * 64, nbase = wn * 64;

    __shared__ int s_tick;
    __shared__ float rbuf[4];
    __shared__ int   rcnt[4];

    float* sqI = (float*)(smem + SM_STG);
    float* sqJ = (float*)(smem + SM_STG + 512);
    int*   lbI = (int*)  (smem + SM_STG + 1024);
    int*   lbJ = (int*)  (smem + SM_STG + 1536);

    if (t == 0) s_tick = (int)atomicAdd(&g_ticket, 1u);
    __syncthreads();
    int cur = s_tick;
    if (cur >= NBLK) return;

    int i0, j0;
    decode_tile(cur, i0, j0);

    // prologue: issue chunks 0..2 of the first tile (chunk 3 issued at c==0)
    #pragma unroll
    for (int c = 0; c < 3; c++) {
        issue_chunk(sbase, i0, j0, c, c, t);
        cp_commit();
    }

    for (;;) {
        if (t == 0) s_tick = (int)atomicAdd(&g_ticket, 1u);
        // stage sq/labels for current tile (safe: previous epilogue read is
        // sealed by the reduction barrier; visibility via chunk barriers)
        sqI[t] = g_sq[i0 + t];  lbI[t] = g_lab[i0 + t];
        sqJ[t] = g_sq[j0 + t];  lbJ[t] = g_lab[j0 + t];

        float acc[4][8][4];
        #pragma unroll
        for (int mf = 0; mf < 4; mf++)
            #pragma unroll
            for (int nf = 0; nf < 8; nf++)
                #pragma unroll
                for (int rr = 0; rr < 4; rr++) acc[mf][nf][rr] = 0.0f;

        int nxt = NBLK, ni0 = 0, nj0 = 0;
        bool more = false;

        // continuous ring: iter c — wait chunk c; barrier; issue chunk c+3
        // (buffer (c+3)&3, whose old contents were computed at iter c-1);
        // commit; compute chunk c.
        #pragma unroll
        for (int c = 0; c < NCHUNK; c++) {
            cp_wait<2>();
            __syncthreads();                 // data visible + compute(c-1) done

            if (c == 0) {
                nxt = s_tick;                // ticket visible after barrier
                more = (nxt < NBLK);
                if (more) decode_tile(nxt, ni0, nj0);
                issue_chunk(sbase, i0, j0, 3, 3, t);      // cur chunk 3
            } else if (more) {
                issue_chunk(sbase, ni0, nj0, c - 1, c - 1, t);  // nxt chunk c-1
            }
            cp_commit();                     // possibly empty; keeps FIFO count

            const uint32_t* Ac = (const uint32_t*)(smem + SM_A + c * ACH);
            const uint32_t* Bc = (const uint32_t*)(smem + SM_B + c * BCH);

            #pragma unroll
            for (int g = 0; g < 2; g++) {    // 2 k16 steps per chunk
                int kb = g * 8;
                uint32_t a[4][4];
                #pragma unroll
                for (int mf = 0; mf < 4; mf++) {
                    const uint32_t* r0 = Ac + (size_t)(mbase + 16 * mf + gid) * PITCHW + kb;
                    const uint32_t* r1 = Ac + (size_t)(mbase + 16 * mf + gid + 8) * PITCHW + kb;
                    a[mf][0] = r0[tig];
                    a[mf][1] = r1[tig];
                    a[mf][2] = r0[tig + 4];
                    a[mf][3] = r1[tig + 4];
                }
                uint32_t b[8][2];
                #pragma unroll
                for (int nf = 0; nf < 8; nf++) {
                    const uint32_t* rn = Bc + (size_t)(nbase + 8 * nf + gid) * PITCHW + kb;
                    b[nf][0] = rn[tig];
                    b[nf][1] = rn[tig + 4];
                }
                #pragma unroll
                for (int mf = 0; mf < 4; mf++)
                    #pragma unroll
                    for (int nf = 0; nf < 8; nf++)
                        mma_f16(acc[mf][nf], a[mf][0], a[mf][1], a[mf][2], a[mf][3],
                                b[nf][0], b[nf][1]);
            }
        }

        // ---- fused epilogue; diag-specialized pair filter ----
        float lsum = 0.0f;
        int   lcnt = 0;
        bool diag = (i0 == j0);
        #pragma unroll
        for (int mf = 0; mf < 4; mf++) {
            #pragma unroll
            for (int rr = 0; rr < 2; rr++) {
                int m  = mbase + 16 * mf + gid + 8 * rr;
                float sqi = sqI[m];
                int   li  = lbI[m];
                #pragma unroll
                for (int nf = 0; nf < 8; nf++) {
                    #pragma unroll
                    for (int cc = 0; cc < 2; cc++) {
                        int n = nbase + 8 * nf + tig * 2 + cc;
                        if (diag && n <= m) continue;   // only diag tiles filter
                        float dot = acc[mf][nf][rr * 2 + cc];
                        float d2 = fmaxf(sqi + sqJ[n] - 2.0f * dot, 0.0f);
                        if (li == lbJ[n]) {
                            lsum += d2;
                            lcnt++;
                        } else if (d2 < MARGIN * MARGIN) {   // ~never (8 sigma)
                            float h = MARGIN - sqrtf(d2);
                            lsum += h * h;
                        }
                    }
                }
            }
        }

        #pragma unroll
        for (int off = 16; off; off >>= 1) {
            lsum += __shfl_xor_sync(0xffffffffu, lsum, off);
            lcnt += __shfl_xor_sync(0xffffffffu, lcnt, off);
        }
        if (lane == 0) { rbuf[wid] = lsum; rcnt[wid] = lcnt; }
        __syncthreads();                      // reduction barrier (seals epilogue)
        if (t == 0) {
            float s = 0.0f; long long c = 0;
            #pragma unroll
            for (int wd = 0; wd < 4; wd++) { s += rbuf[wd]; c += rcnt[wd]; }
            g_partials[cur] = s * 2.0f;
            g_poscnt[cur]   = c * 2LL;
        }

        if (!more) break;
        cur = nxt; i0 = ni0; j0 = nj0;
    }
}

// ---------------------------------------------------------------------------
__global__ void finalize_kernel(float* __restrict__ out) {
    int t = threadIdx.x;
    double s = 0.0; long long c = 0;
    for (int i = t; i < NBLK; i += 256) {
        s += (double)g_partials[i];
        c += g_poscnt[i];
    }
    __shared__ double    sd[256];
    __shared__ long long sc[256];
    sd[t] = s; sc[t] = c;
    __syncthreads();
    for (int off = 128; off; off >>= 1) {
        if (t < off) { sd[t] += sd[t + off]; sc[t] += sc[t + off]; }
        __syncthreads();
    }
    if (t == 0) {
        double total = sd[0];
        double denom = (double)((long long)BN * (BN - 1));
        out[0] = (float)(sc[0] > 0 ? total / denom : total);
    }
}

// ---------------------------------------------------------------------------
extern "C" void kernel_launch(void* const* d_in, const int* in_sizes, int n_in,
                              void* d_out, int out_size) {
    const float* F      = (const float*)d_in[0];
    const void*  labels = d_in[1];
    float*       out    = (float*)d_out;

    cudaFuncSetAttribute(tile_kernel,
                         cudaFuncAttributeMaxDynamicSharedMemorySize, SM_TOT);

    prep_kernel<<<BN / 8, 256>>>(F, labels);
    tile_kernel<<<NPERS, 128, SM_TOT>>>();
    finalize_kernel<<<1, 256>>>(out);
}

// round 17
// speedup vs baseline: 2.7279x; 1.2923x over previous
#include <cuda_runtime.h>
#include <cuda_fp16.h>
#include <cstdint>

// FeaturesLoss: mma.sync m16n8k16 fp16/f32acc, persistent 256-thread CTAs
// (2/SM -> 4 warps/SMSP), 8 warps x 64x32 warp-tiles over 128x128 tiles,
// 4-chunk cp.async ring across tiles, ordered-pair (j>i, x2) coverage,
// deterministic per-tile partials + fixed-order finalize.

#define BN    8192
#define DIM   128
#define TM    128
#define NT    (BN / TM)             // 64
#define NBLK  (NT * (NT + 1) / 2)   // 2080 upper-tri tiles
#define MARGIN 2.0f
#define NPERS (152 * 2)

#define NCHUNK 4                    // K chunks of 32 (fp16: 64 B per row)
#define PITCH  80                   // bytes per row per chunk (20 words)
#define PITCHW 20
#define ACH    (TM * PITCH)         // 10240
#define BCH    (TM * PITCH)         // 10240
#define SM_A   0
#define SM_B   (NCHUNK * ACH)       // 40960
#define SM_STG (SM_B + NCHUNK * BCH)// 81920
#define STGSZ  2048                 // sqI/sqJ/lbI/lbJ (512 B each)
#define SM_TOT (SM_STG + 2 * STGSZ) // 86016 B per CTA (x2 CTAs = 172 KB/SM)

__device__ float      g_sq[BN];
__device__ int        g_lab[BN];
__device__ uint32_t   g_f16[BN * DIM / 2];   // packed half2, natural k order
__device__ float      g_partials[NBLK];
__device__ long long  g_poscnt[NBLK];
__device__ unsigned   g_ticket;

__device__ __forceinline__ uint32_t smem_u32(const void* p) {
    uint32_t a;
    asm("{ .reg .u64 t; cvta.to.shared.u64 t, %1; cvt.u32.u64 %0, t; }" : "=r"(a) : "l"(p));
    return a;
}
__device__ __forceinline__ void cp16(uint32_t dst, const void* src) {
    asm volatile("cp.async.cg.shared.global [%0], [%1], 16;" :: "r"(dst), "l"(src));
}
__device__ __forceinline__ void cp_commit() {
    asm volatile("cp.async.commit_group;" ::: "memory");
}
template<int N> __device__ __forceinline__ void cp_wait() {
    asm volatile("cp.async.wait_group %0;" :: "n"(N) : "memory");
}
__device__ __forceinline__ void mma_f16(float c[4], uint32_t a0, uint32_t a1,
                                        uint32_t a2, uint32_t a3,
                                        uint32_t b0, uint32_t b1) {
    asm volatile(
        "mma.sync.aligned.m16n8k16.row.col.f32.f16.f16.f32 "
        "{%0,%1,%2,%3}, {%4,%5,%6,%7}, {%8,%9}, {%0,%1,%2,%3};"
        : "+f"(c[0]), "+f"(c[1]), "+f"(c[2]), "+f"(c[3])
        : "r"(a0), "r"(a1), "r"(a2), "r"(a3), "r"(b0), "r"(b1));
}
__device__ __forceinline__ void decode_tile(int idx, int& i0, int& j0) {
    int bi = 0;
    while (idx >= NT - bi) { idx -= NT - bi; bi++; }
    i0 = bi * TM;
    j0 = (bi + idx) * TM;
}

// ---------------------------------------------------------------------------
// Kernel 0: norms (exact fp32), labels (int64/int32 probe), fp16 packed copy.
// ---------------------------------------------------------------------------
__global__ void prep_kernel(const float* __restrict__ F,
                            const void* __restrict__ labels_raw) {
    if (blockIdx.x == 0 && threadIdx.x == 0) g_ticket = 0;  // reset per replay

    int warp = (blockIdx.x * blockDim.x + threadIdx.x) >> 5;
    int lane = threadIdx.x & 31;
    if (warp >= BN) return;

    const int* w = (const int*)labels_raw;
    int probe = w[2 * lane + 1];
    unsigned is64 = __all_sync(0xffffffffu, probe == 0);

    const float4* row = (const float4*)(F + (size_t)warp * DIM);
    float4 f = row[lane];

    __half2 h0 = __floats2half2_rn(f.x, f.y);
    __half2 h1 = __floats2half2_rn(f.z, f.w);
    uint2 hp = { *(uint32_t*)&h0, *(uint32_t*)&h1 };
    *(uint2*)&g_f16[(size_t)warp * 64 + lane * 2] = hp;

    float s = f.x * f.x + f.y * f.y + f.z * f.z + f.w * f.w;
    #pragma unroll
    for (int off = 16; off; off >>= 1)
        s += __shfl_xor_sync(0xffffffffu, s, off);

    if (lane == 0) {
        g_sq[warp] = s;
        int lab;
        if (is64) lab = (int)((const long long*)labels_raw)[warp];
        else      lab = w[warp];
        g_lab[warp] = lab;
    }
}

// ---------------------------------------------------------------------------
// Issue cp.async for one K=32 chunk of tile (i0,j0) into ring buffer c.
// 256 threads: A = 512 16B segs (2 rounds), B same.
__device__ __forceinline__ void issue_chunk(uint32_t sbase, int i0, int j0,
                                            int c, int t) {
    const char* P = (const char*)g_f16;           // 256 B per feature row
    #pragma unroll
    for (int s = t; s < TM * 4; s += 256) {
        int r = s >> 2, q = s & 3;
        cp16(sbase + SM_A + c * ACH + r * PITCH + q * 16,
             P + (size_t)(i0 + r) * 256 + c * 64 + q * 16);
    }
    #pragma unroll
    for (int s = t; s < TM * 4; s += 256) {
        int r = s >> 2, q = s & 3;
        cp16(sbase + SM_B + c * BCH + r * PITCH + q * 16,
             P + (size_t)(j0 + r) * 256 + c * 64 + q * 16);
    }
}

// ---------------------------------------------------------------------------
__global__ void __launch_bounds__(256, 2)
tile_kernel() {
    extern __shared__ char smem[];
    uint32_t sbase = smem_u32(smem);

    int t = threadIdx.x;
    int wid = t >> 5, lane = t & 31;
    int gid = lane >> 2, tig = lane & 3;
    int wm = wid & 1, wn = wid >> 1;     // 2x4 grid: 64-row x 32-col subtiles
    int mbase = wm * 64, nbase = wn * 32;

    __shared__ int s_tick;
    __shared__ float rbuf[8];
    __shared__ int   rcnt[8];

    if (t == 0) s_tick = (int)atomicAdd(&g_ticket, 1u);
    __syncthreads();
    int cur = s_tick;
    if (cur >= NBLK) return;

    int i0, j0;
    decode_tile(cur, i0, j0);

    #pragma unroll
    for (int c = 0; c < NCHUNK; c++) {
        issue_chunk(sbase, i0, j0, c, t);
        cp_commit();
    }

    int parity = 0;
    for (;;) {
        if (t == 0) s_tick = (int)atomicAdd(&g_ticket, 1u);
        if (t < 128) {
            char* stg = smem + SM_STG + parity * STGSZ;
            ((float*)stg)[t]         = g_sq[i0 + t];
            ((float*)(stg + 512))[t] = g_sq[j0 + t];
            ((int*)(stg + 1024))[t]  = g_lab[i0 + t];
            ((int*)(stg + 1536))[t]  = g_lab[j0 + t];
        }
        __syncthreads();
        int nxt = s_tick;
        int ni0 = 0, nj0 = 0;
        bool more = (nxt < NBLK);
        if (more) decode_tile(nxt, ni0, nj0);

        float acc[4][4][4];                  // 64x32 warp tile
        #pragma unroll
        for (int mf = 0; mf < 4; mf++)
            #pragma unroll
            for (int nf = 0; nf < 4; nf++)
                #pragma unroll
                for (int rr = 0; rr < 4; rr++) acc[mf][nf][rr] = 0.0f;

        // ring over 4 K=32 chunks: compute chunk c, refill with next tile's c
        #pragma unroll
        for (int c = 0; c < NCHUNK; c++) {
            cp_wait<3>();
            __syncthreads();

            const uint32_t* Ac = (const uint32_t*)(smem + SM_A + c * ACH);
            const uint32_t* Bc = (const uint32_t*)(smem + SM_B + c * BCH);

            #pragma unroll
            for (int g = 0; g < 2; g++) {    // 2 k16 steps per chunk
                int kb = g * 8;
                uint32_t a[4][4];
                #pragma unroll
                for (int mf = 0; mf < 4; mf++) {
                    const uint32_t* r0 = Ac + (size_t)(mbase + 16 * mf + gid) * PITCHW + kb;
                    const uint32_t* r1 = Ac + (size_t)(mbase + 16 * mf + gid + 8) * PITCHW + kb;
                    a[mf][0] = r0[tig];
                    a[mf][1] = r1[tig];
                    a[mf][2] = r0[tig + 4];
                    a[mf][3] = r1[tig + 4];
                }
                uint32_t b[4][2];
                #pragma unroll
                for (int nf = 0; nf < 4; nf++) {
                    const uint32_t* rn = Bc + (size_t)(nbase + 8 * nf + gid) * PITCHW + kb;
                    b[nf][0] = rn[tig];
                    b[nf][1] = rn[tig + 4];
                }
                #pragma unroll
                for (int mf = 0; mf < 4; mf++)
                    #pragma unroll
                    for (int nf = 0; nf < 4; nf++)
                        mma_f16(acc[mf][nf], a[mf][0], a[mf][1], a[mf][2], a[mf][3],
                                b[nf][0], b[nf][1]);
            }

            __syncthreads();
            if (more) issue_chunk(sbase, ni0, nj0, c, t);
            cp_commit();
        }

        // ---- fused epilogue: ordered pairs gj > gi, weight x2 ----
        const char* stg = smem + SM_STG + parity * STGSZ;
        const float* sqI = (const float*)stg;
        const float* sqJ = (const float*)(stg + 512);
        const int*   lbI = (const int*)(stg + 1024);
        const int*   lbJ = (const int*)(stg + 1536);

        float lsum = 0.0f;
        int   lcnt = 0;
        bool diag = (i0 == j0);
        #pragma unroll
        for (int mf = 0; mf < 4; mf++) {
            #pragma unroll
            for (int rr = 0; rr < 2; rr++) {
                int m = mbase + 16 * mf + gid + 8 * rr;
                float sqi = sqI[m];
                int   li  = lbI[m];
                #pragma unroll
                for (int nf = 0; nf < 4; nf++) {
                    #pragma unroll
                    for (int cc = 0; cc < 2; cc++) {
                        int n = nbase + 8 * nf + tig * 2 + cc;
                        if (diag && n <= m) continue;
                        float dot = acc[mf][nf][rr * 2 + cc];
                        float d2 = fmaxf(sqi + sqJ[n] - 2.0f * dot, 0.0f);
                        if (li == lbJ[n]) {
                            lsum += d2;
                            lcnt++;
                        } else if (d2 < MARGIN * MARGIN) {   // ~never (8 sigma)
                            float h = MARGIN - sqrtf(d2);
                            lsum += h * h;
                        }
                    }
                }
            }
        }

        #pragma unroll
        for (int off = 16; off; off >>= 1) {
            lsum += __shfl_xor_sync(0xffffffffu, lsum, off);
            lcnt += __shfl_xor_sync(0xffffffffu, lcnt, off);
        }
        if (lane == 0) { rbuf[wid] = lsum; rcnt[wid] = lcnt; }
        __syncthreads();
        if (t == 0) {
            float s = 0.0f; long long c = 0;
            #pragma unroll
            for (int wd = 0; wd < 8; wd++) { s += rbuf[wd]; c += rcnt[wd]; }
            g_partials[cur] = s * 2.0f;
            g_poscnt[cur]   = c * 2LL;
        }

        if (!more) break;
        cur = nxt; i0 = ni0; j0 = nj0; parity ^= 1;
    }
}

// ---------------------------------------------------------------------------
__global__ void finalize_kernel(float* __restrict__ out) {
    int t = threadIdx.x;
    double s = 0.0; long long c = 0;
    for (int i = t; i < NBLK; i += 256) {
        s += (double)g_partials[i];
        c += g_poscnt[i];
    }
    __shared__ double    sd[256];
    __shared__ long long sc[256];
    sd[t] = s; sc[t] = c;
    __syncthreads();
    for (int off = 128; off; off >>= 1) {
        if (t < off) { sd[t] += sd[t + off]; sc[t] += sc[t + off]; }
        __syncthreads();
    }
    if (t == 0) {
        double total = sd[0];
        double denom = (double)((long long)BN * (BN - 1));
        out[0] = (float)(sc[0] > 0 ? total / denom : total);
    }
}

// ---------------------------------------------------------------------------
extern "C" void kernel_launch(void* const* d_in, const int* in_sizes, int n_in,
                              void* d_out, int out_size) {
    const float* F      = (const float*)d_in[0];
    const void*  labels = d_in[1];
    float*       out    = (float*)d_out;

    cudaFuncSetAttribute(tile_kernel,
                         cudaFuncAttributeMaxDynamicSharedMemorySize, SM_TOT);

    prep_kernel<<<BN / 8, 256>>>(F, labels);
    tile_kernel<<<NPERS, 256, SM_TOT>>>();
    finalize_kernel<<<1, 256>>>(out);
}